// round 1
// baseline (speedup 1.0000x reference)
#include <cuda_runtime.h>

// Problem constants (fixed by the dataset)
#define B_  2
#define L_  192
#define D_  768
#define NC_ 4
#define H_  256

// Scratch for projection outputs (no cudaMalloc allowed)
__device__ float g_hp[B_ * L_ * H_];            // [B*L, H]
__device__ float g_ha[B_ * L_ * NC_ * H_];      // [B*L, NC*H]

// ---------------------------------------------------------------------------
// Helpers
// ---------------------------------------------------------------------------

// Accurate-enough branch-free tanh: 1 - 2/(exp(2x)+1).
// __expf -> MUFU.EX2 path, __fdividef -> MUFU.RCP path. rel err ~1e-6.
// Saturates correctly: x->+inf => exp->inf => 1-0 = 1; x->-inf => 1-2 = -1.
__device__ __forceinline__ float fast_tanh(float x) {
    float e = __expf(2.0f * x);
    return 1.0f - __fdividef(2.0f, e + 1.0f);
}

__device__ __forceinline__ unsigned long long pack2(float x) {
    unsigned long long r;
    asm("mov.b64 %0, {%1, %1};" : "=l"(r) : "f"(x));
    return r;
}

__device__ __forceinline__ unsigned long long ffma2(unsigned long long a,
                                                    unsigned long long b,
                                                    unsigned long long c) {
    unsigned long long d;
    asm("fma.rn.f32x2 %0, %1, %2, %3;" : "=l"(d) : "l"(a), "l"(b), "l"(c));
    return d;
}

__device__ __forceinline__ void unpack2(unsigned long long v, float& lo, float& hi) {
    asm("mov.b64 {%0, %1}, %2;" : "=f"(lo), "=f"(hi) : "l"(v));
}

// ---------------------------------------------------------------------------
// Kernel 1: projections  h_p = seq@Wp + bp, h_a = seq@Wa + ba
// Treated as one GEMM: [384, 768] x [768, 1280] with column-dependent weight src.
// Tile 64x64, 256 threads, 4x4 micro-tile.
// ---------------------------------------------------------------------------
__global__ __launch_bounds__(256) void proj_kernel(
    const float* __restrict__ seq,
    const float* __restrict__ Wp, const float* __restrict__ bp,
    const float* __restrict__ Wa, const float* __restrict__ ba)
{
    __shared__ __align__(16) float As[16][68];   // [k][m], padded
    __shared__ __align__(16) float Bs[16][64];   // [k][n]

    const int tid = threadIdx.x;
    const int tx = tid & 15;        // n micro-block
    const int ty = tid >> 4;        // m micro-block
    const int m0 = blockIdx.y * 64;
    const int n0 = blockIdx.x * 64;

    const float* Wsrc;
    int ld, coff;
    if (n0 < H_) { Wsrc = Wp; ld = H_;        coff = n0; }
    else         { Wsrc = Wa; ld = NC_ * H_;  coff = n0 - H_; }

    float acc[4][4];
#pragma unroll
    for (int i = 0; i < 4; i++)
#pragma unroll
        for (int j = 0; j < 4; j++) acc[i][j] = 0.0f;

#pragma unroll 1
    for (int kc = 0; kc < D_; kc += 16) {
        __syncthreads();
        {   // load A tile (store transposed [k][m]), coalesced over k
            const int k = tid & 15, mloc = tid >> 4;
#pragma unroll
            for (int ps = 0; ps < 4; ps++) {
                const int m = mloc + ps * 16;
                As[k][m] = seq[(m0 + m) * D_ + kc + k];
            }
        }
        {   // load B tile, coalesced over n
            const int c = tid & 63, kr = tid >> 6;
#pragma unroll
            for (int ps = 0; ps < 4; ps++) {
                const int k = kr + ps * 4;
                Bs[k][c] = Wsrc[(kc + k) * ld + coff + c];
            }
        }
        __syncthreads();
#pragma unroll
        for (int k = 0; k < 16; k++) {
            const float4 a4 = *(const float4*)&As[k][ty * 4];
            const float4 b4 = *(const float4*)&Bs[k][tx * 4];
            const float av[4] = {a4.x, a4.y, a4.z, a4.w};
            const float bv[4] = {b4.x, b4.y, b4.z, b4.w};
#pragma unroll
            for (int i = 0; i < 4; i++)
#pragma unroll
                for (int j = 0; j < 4; j++)
                    acc[i][j] = fmaf(av[i], bv[j], acc[i][j]);
        }
    }

    // store with bias
#pragma unroll
    for (int i = 0; i < 4; i++) {
        const int r = m0 + ty * 4 + i;
#pragma unroll
        for (int j = 0; j < 4; j++) {
            const int cg = n0 + tx * 4 + j;
            const float v = acc[i][j];
            if (cg < H_) {
                g_hp[r * H_ + cg] = v + bp[cg];
            } else {
                const int c2 = cg - H_;
                g_ha[r * (NC_ * H_) + c2] = v + ba[c2];
            }
        }
    }
}

// ---------------------------------------------------------------------------
// Kernel 2: fused refinement.
// Per block: (b, n, p-tile of 8, a-tile of 16) => M=128 rows (p,a pairs),
// N = 256 (all mid outputs), K = 256 chunked by 16.
// X[m,k] = tanh(h_p[p,k] + h_a[a,n,k]) computed into SMEM per chunk.
// Epilogue: += bs-tail + bmid, tanh, dot Wout, half-warp reduce -> out[b,p,n,a].
// ---------------------------------------------------------------------------
__global__ __launch_bounds__(256, 1) void refine_kernel(
    const float* __restrict__ bscore,   // [B, L, NC, L]
    const float* __restrict__ Wmid,     // [NC, H+NC, H]
    const float* __restrict__ bmid,     // [NC, H]
    const float* __restrict__ Wout,     // [NC, H]
    float* __restrict__ out)            // [B, L, NC, L]  ([b,p,n,a])
{
    __shared__ float hp_s[8][17];
    __shared__ float ha_s[16][17];
    __shared__ __align__(16) float Xs[16][132];     // [k][m]
    __shared__ __align__(16) float Ws[16][256];     // [k][j]
    __shared__ float Wtail[4][256];
    __shared__ float bmid_s[256];
    __shared__ float Wout_s[256];

    const int tid = threadIdx.x;
    const int tx = tid & 15;    // owns N columns [tx*16, tx*16+16)
    const int ty = tid >> 4;    // owns M rows    [ty*8,  ty*8+8)
    const int bz = blockIdx.z;
    const int b = bz >> 2, n = bz & 3;
    const int p0 = blockIdx.y * 8;
    const int a0 = blockIdx.x * 16;

    const float* Wn = Wmid + n * (H_ + NC_) * H_;

    // epilogue constants (synced by the barriers inside the K loop)
#pragma unroll
    for (int q = 0; q < 4; q++) {
        const int i = q * 256 + tid;
        Wtail[i >> 8][i & 255] = Wn[(H_ + (i >> 8)) * H_ + (i & 255)];
    }
    bmid_s[tid] = bmid[n * H_ + tid];
    Wout_s[tid] = Wout[n * H_ + tid];

    const float* hp = g_hp + (b * L_ + p0) * H_;
    const float* ha = g_ha + (b * L_ + a0) * (NC_ * H_) + n * H_;

    unsigned long long acc[8][8];   // [m][j-pair], each = f32x2
#pragma unroll
    for (int i = 0; i < 8; i++)
#pragma unroll
        for (int j = 0; j < 8; j++) acc[i][j] = 0ull;

#pragma unroll 1
    for (int kc = 0; kc < H_; kc += 16) {
        __syncthreads();
        // load hp tile 8x16
        if (tid < 128) {
            const int r = tid >> 4, c = tid & 15;
            hp_s[r][c] = hp[r * H_ + kc + c];
        }
        // load ha tile 16x16
        {
            const int r = tid >> 4, c = tid & 15;
            ha_s[r][c] = ha[r * (NC_ * H_) + kc + c];
        }
        // load W chunk 16x256 via float4 (coalesced)
        {
            const float4* src = (const float4*)(Wn + kc * H_);
#pragma unroll
            for (int q = 0; q < 4; q++) {
                const int lin = q * 256 + tid;
                const int row = lin >> 6, c4 = lin & 63;
                ((float4*)&Ws[row][0])[c4] = src[row * 64 + c4];
            }
        }
        __syncthreads();
        // build X tile: Xs[k][m] = tanh(hp[p(m),k] + ha[a(m),n,k])
        {
            const int kk = tid & 15, g = tid >> 4;
            const float hpv = hp_s[g >> 1][kk];
#pragma unroll
            for (int i = 0; i < 8; i++) {
                const int m = g * 8 + i;
                Xs[kk][m] = fast_tanh(hpv + ha_s[m & 15][kk]);
            }
        }
        __syncthreads();
        // GEMM: 16 rank-1 updates of the 8x16 micro tile (as 8x8 f32x2)
#pragma unroll
        for (int k = 0; k < 16; k++) {
            const float4 x0 = *(const float4*)&Xs[k][ty * 8];
            const float4 x1 = *(const float4*)&Xs[k][ty * 8 + 4];
            const ulonglong2* wr = (const ulonglong2*)&Ws[k][tx * 16];
            const ulonglong2 w01 = wr[0], w23 = wr[1], w45 = wr[2], w67 = wr[3];
            const unsigned long long w[8] = {w01.x, w01.y, w23.x, w23.y,
                                             w45.x, w45.y, w67.x, w67.y};
            const float xm[8] = {x0.x, x0.y, x0.z, x0.w, x1.x, x1.y, x1.z, x1.w};
#pragma unroll
            for (int mi = 0; mi < 8; mi++) {
                const unsigned long long xp = pack2(xm[mi]);
#pragma unroll
                for (int jj = 0; jj < 8; jj++)
                    acc[mi][jj] = ffma2(xp, w[jj], acc[mi][jj]);
            }
        }
    }

    // Epilogue: bs-tail + bias, tanh, dot with Wout, reduce over tx (16 lanes)
#pragma unroll 1
    for (int i = 0; i < 8; i++) {
        const int m = ty * 8 + i;
        const int p = p0 + (m >> 4);
        const int a = a0 + (m & 15);
        const float* bsp = bscore + ((b * L_ + p) * NC_) * L_ + a;
        const float c0 = bsp[0];
        const float c1 = bsp[L_];
        const float c2 = bsp[2 * L_];
        const float c3 = bsp[3 * L_];
        float partial = 0.0f;
#pragma unroll
        for (int jj = 0; jj < 8; jj++) {
            float lo, hi;
            unpack2(acc[i][jj], lo, hi);
            const int j = tx * 16 + jj * 2;
            float t0 = lo + bmid_s[j];
            t0 = fmaf(c0, Wtail[0][j], t0);
            t0 = fmaf(c1, Wtail[1][j], t0);
            t0 = fmaf(c2, Wtail[2][j], t0);
            t0 = fmaf(c3, Wtail[3][j], t0);
            float t1 = hi + bmid_s[j + 1];
            t1 = fmaf(c0, Wtail[0][j + 1], t1);
            t1 = fmaf(c1, Wtail[1][j + 1], t1);
            t1 = fmaf(c2, Wtail[2][j + 1], t1);
            t1 = fmaf(c3, Wtail[3][j + 1], t1);
            partial = fmaf(fast_tanh(t0), Wout_s[j], partial);
            partial = fmaf(fast_tanh(t1), Wout_s[j + 1], partial);
        }
        // reduce over the 16 lanes (tx) sharing this m (width-16 shuffle)
#pragma unroll
        for (int off = 8; off > 0; off >>= 1)
            partial += __shfl_down_sync(0xFFFFFFFFu, partial, off, 16);
        if (tx == 0)
            out[((b * L_ + p) * NC_ + n) * L_ + a] = partial;
    }
}

// ---------------------------------------------------------------------------
// Launch
// ---------------------------------------------------------------------------
extern "C" void kernel_launch(void* const* d_in, const int* in_sizes, int n_in,
                              void* d_out, int out_size) {
    const float* seq    = (const float*)d_in[0];
    const float* bscore = (const float*)d_in[1];
    const float* Wp     = (const float*)d_in[2];
    const float* bp     = (const float*)d_in[3];
    const float* Wa     = (const float*)d_in[4];
    const float* ba     = (const float*)d_in[5];
    const float* Wmid   = (const float*)d_in[6];
    const float* bmid   = (const float*)d_in[7];
    const float* Wout   = (const float*)d_in[8];
    float* out = (float*)d_out;

    // Projections: [384,768] x [768,1280]
    proj_kernel<<<dim3((H_ + NC_ * H_) / 64, (B_ * L_) / 64), 256>>>(
        seq, Wp, bp, Wa, ba);

    // Fused refinement: grid (a-tiles, p-tiles, b*NC) = (12, 24, 8)
    refine_kernel<<<dim3(L_ / 16, L_ / 8, B_ * NC_), 256>>>(
        bscore, Wmid, bmid, Wout, out);
}

// round 2
// speedup vs baseline: 1.4523x; 1.4523x over previous
#include <cuda_runtime.h>
#include <cstdint>

// Problem constants (fixed by the dataset)
#define B_  2
#define L_  192
#define D_  768
#define NC_ 4
#define H_  256
#define KC  16      // k-chunk size in refine kernel

// Scratch for projection outputs (no cudaMalloc allowed)
__device__ float g_hp[B_ * L_ * H_];            // [B*L, H]
__device__ float g_ha[B_ * L_ * NC_ * H_];      // [B*L, NC*H]

// ---------------------------------------------------------------------------
// Helpers
// ---------------------------------------------------------------------------
__device__ __forceinline__ float fast_tanh(float x) {
    float e = __expf(2.0f * x);
    return 1.0f - __fdividef(2.0f, e + 1.0f);
}

__device__ __forceinline__ unsigned long long pack2(float x) {
    unsigned long long r;
    asm("mov.b64 %0, {%1, %1};" : "=l"(r) : "f"(x));
    return r;
}

__device__ __forceinline__ unsigned long long ffma2(unsigned long long a,
                                                    unsigned long long b,
                                                    unsigned long long c) {
    unsigned long long d;
    asm("fma.rn.f32x2 %0, %1, %2, %3;" : "=l"(d) : "l"(a), "l"(b), "l"(c));
    return d;
}

__device__ __forceinline__ void unpack2(unsigned long long v, float& lo, float& hi) {
    asm("mov.b64 {%0, %1}, %2;" : "=f"(lo), "=f"(hi) : "l"(v));
}

__device__ __forceinline__ void cp_async16(uint32_t smem, const void* gptr) {
    asm volatile("cp.async.cg.shared.global [%0], [%1], 16;" :: "r"(smem), "l"(gptr));
}
__device__ __forceinline__ void cp_commit() {
    asm volatile("cp.async.commit_group;");
}
__device__ __forceinline__ void cp_wait_all() {
    asm volatile("cp.async.wait_group 0;" ::: "memory");
}

// ---------------------------------------------------------------------------
// Kernel 1: projections  h_p = seq@Wp + bp, h_a = seq@Wa + ba
// ---------------------------------------------------------------------------
__global__ __launch_bounds__(256) void proj_kernel(
    const float* __restrict__ seq,
    const float* __restrict__ Wp, const float* __restrict__ bp,
    const float* __restrict__ Wa, const float* __restrict__ ba)
{
    __shared__ __align__(16) float As[16][68];   // [k][m], padded
    __shared__ __align__(16) float Bs[16][64];   // [k][n]

    const int tid = threadIdx.x;
    const int tx = tid & 15;
    const int ty = tid >> 4;
    const int m0 = blockIdx.y * 64;
    const int n0 = blockIdx.x * 64;

    const float* Wsrc;
    int ld, coff;
    if (n0 < H_) { Wsrc = Wp; ld = H_;        coff = n0; }
    else         { Wsrc = Wa; ld = NC_ * H_;  coff = n0 - H_; }

    float acc[4][4];
#pragma unroll
    for (int i = 0; i < 4; i++)
#pragma unroll
        for (int j = 0; j < 4; j++) acc[i][j] = 0.0f;

#pragma unroll 1
    for (int kc = 0; kc < D_; kc += 16) {
        __syncthreads();
        {
            const int k = tid & 15, mloc = tid >> 4;
#pragma unroll
            for (int ps = 0; ps < 4; ps++) {
                const int m = mloc + ps * 16;
                As[k][m] = seq[(m0 + m) * D_ + kc + k];
            }
        }
        {
            const int c = tid & 63, kr = tid >> 6;
#pragma unroll
            for (int ps = 0; ps < 4; ps++) {
                const int k = kr + ps * 4;
                Bs[k][c] = Wsrc[(kc + k) * ld + coff + c];
            }
        }
        __syncthreads();
#pragma unroll
        for (int k = 0; k < 16; k++) {
            const float4 a4 = *(const float4*)&As[k][ty * 4];
            const float4 b4 = *(const float4*)&Bs[k][tx * 4];
            const float av[4] = {a4.x, a4.y, a4.z, a4.w};
            const float bv[4] = {b4.x, b4.y, b4.z, b4.w};
#pragma unroll
            for (int i = 0; i < 4; i++)
#pragma unroll
                for (int j = 0; j < 4; j++)
                    acc[i][j] = fmaf(av[i], bv[j], acc[i][j]);
        }
    }

#pragma unroll
    for (int i = 0; i < 4; i++) {
        const int r = m0 + ty * 4 + i;
#pragma unroll
        for (int j = 0; j < 4; j++) {
            const int cg = n0 + tx * 4 + j;
            const float v = acc[i][j];
            if (cg < H_) {
                g_hp[r * H_ + cg] = v + bp[cg];
            } else {
                const int c2 = cg - H_;
                g_ha[r * (NC_ * H_) + c2] = v + ba[c2];
            }
        }
    }
}

// ---------------------------------------------------------------------------
// Kernel 2: fused refinement (pipelined, conflict-free SMEM)
// Block: (b, n, 8 p-rows x 16 a-rows) -> M=128, N=256, K=256 in chunks of 16.
// Thread (tx,ty): M rows [ty*8, ty*8+8), N cols {tx*4 + 64q + 0..3 : q=0..3}.
// ---------------------------------------------------------------------------
struct __align__(16) SmemT {
    float hp[8][256];          // persistent h_p rows
    float ha[16][258];         // persistent h_a rows (pad 258: bank-split halves)
    float Xs[2][KC][132];      // double-buffered X tile [k][m]
    float Ws[2][KC][256];      // double-buffered W chunk [k][j]
    float Wtail[4][256];
    float bmid[256];
    float Wout[256];
};

__global__ __launch_bounds__(256, 1) void refine_kernel(
    const float* __restrict__ bscore,   // [B, L, NC, L]
    const float* __restrict__ Wmid,     // [NC, H+NC, H]
    const float* __restrict__ bmid,     // [NC, H]
    const float* __restrict__ Wout,     // [NC, H]
    float* __restrict__ out)            // [B, L, NC, L]
{
    extern __shared__ char smem_raw[];
    SmemT& S = *reinterpret_cast<SmemT*>(smem_raw);

    const int tid = threadIdx.x;
    const int tx = tid & 15;
    const int ty = tid >> 4;
    const int bz = blockIdx.z;
    const int b = bz >> 2, n = bz & 3;
    const int p0 = blockIdx.y * 8;
    const int a0 = blockIdx.x * 16;

    const float* Wn = Wmid + n * (H_ + NC_) * H_;
    const float* hp_g = g_hp + (b * L_ + p0) * H_;
    const float* ha_g = g_ha + (b * L_ + a0) * (NC_ * H_) + n * H_;

    // ---- init: persistent tiles + epilogue constants ----
    // hp: 8x256 contiguous -> straight float4 copy
    {
        const float4* src = (const float4*)hp_g;
        float4* dst = (float4*)&S.hp[0][0];
#pragma unroll
        for (int q = 0; q < 2; q++) dst[q * 256 + tid] = src[q * 256 + tid];
    }
    // ha: 16 rows, global row stride NC_*H_; padded smem rows -> scalar stores
#pragma unroll
    for (int q = 0; q < 4; q++) {
        const int lin = q * 256 + tid;
        const int r = lin >> 6, c4 = lin & 63;
        const float4 v = ((const float4*)(ha_g + r * (NC_ * H_)))[c4];
        S.ha[r][c4 * 4 + 0] = v.x;
        S.ha[r][c4 * 4 + 1] = v.y;
        S.ha[r][c4 * 4 + 2] = v.z;
        S.ha[r][c4 * 4 + 3] = v.w;
    }
#pragma unroll
    for (int q = 0; q < 4; q++) {
        const int i = q * 256 + tid;
        S.Wtail[i >> 8][i & 255] = Wn[(H_ + (i >> 8)) * H_ + (i & 255)];
    }
    S.bmid[tid] = bmid[n * H_ + tid];
    S.Wout[tid] = Wout[n * H_ + tid];
    __syncthreads();

    // build-thread mapping: m = tid&127 (one m-row), 8 k's per thread
    const int bm = tid & 127;
    const int bkoff = (tid >> 7) * 8;
    const int bp_row = bm >> 4;
    const int ba_row = bm & 15;

    // ---- prologue: X chunk 0 + async W chunk 0 ----
    {
        // W chunk 0 -> Ws[0] (16KB contiguous)
        const float4* src = (const float4*)Wn;
        uint32_t dst = (uint32_t)__cvta_generic_to_shared(&S.Ws[0][0][0]);
#pragma unroll
        for (int q = 0; q < 4; q++) {
            const int idx = q * 256 + tid;
            cp_async16(dst + idx * 16, src + idx);
        }
        cp_commit();
        // X chunk 0
#pragma unroll
        for (int kk = 0; kk < 8; kk++) {
            const int k = bkoff + kk;
            S.Xs[0][k][bm] = fast_tanh(S.hp[bp_row][k] + S.ha[ba_row][k]);
        }
    }
    cp_wait_all();
    __syncthreads();

    unsigned long long acc[8][8];   // [m][j-pair] f32x2
#pragma unroll
    for (int i = 0; i < 8; i++)
#pragma unroll
        for (int j = 0; j < 8; j++) acc[i][j] = 0ull;

#pragma unroll 1
    for (int c = 0; c < H_ / KC; c++) {
        const int buf = c & 1;
        if (c < H_ / KC - 1) {
            // async-load next W chunk
            const float4* src = (const float4*)(Wn + (c + 1) * KC * H_);
            uint32_t dst = (uint32_t)__cvta_generic_to_shared(&S.Ws[buf ^ 1][0][0]);
#pragma unroll
            for (int q = 0; q < 4; q++) {
                const int idx = q * 256 + tid;
                cp_async16(dst + idx * 16, src + idx);
            }
            cp_commit();
            // build next X chunk
            const int kg = (c + 1) * KC + bkoff;
#pragma unroll
            for (int kk = 0; kk < 8; kk++) {
                S.Xs[buf ^ 1][bkoff + kk][bm] =
                    fast_tanh(S.hp[bp_row][kg + kk] + S.ha[ba_row][kg + kk]);
            }
        }
        // GEMM on current buffers
#pragma unroll
        for (int k = 0; k < KC; k++) {
            const float4 x0 = *(const float4*)&S.Xs[buf][k][ty * 8];
            const float4 x1 = *(const float4*)&S.Xs[buf][k][ty * 8 + 4];
            const ulonglong2 w0 = *(const ulonglong2*)&S.Ws[buf][k][tx * 4];
            const ulonglong2 w1 = *(const ulonglong2*)&S.Ws[buf][k][tx * 4 + 64];
            const ulonglong2 w2 = *(const ulonglong2*)&S.Ws[buf][k][tx * 4 + 128];
            const ulonglong2 w3 = *(const ulonglong2*)&S.Ws[buf][k][tx * 4 + 192];
            const unsigned long long w[8] = {w0.x, w0.y, w1.x, w1.y,
                                             w2.x, w2.y, w3.x, w3.y};
            const float xm[8] = {x0.x, x0.y, x0.z, x0.w, x1.x, x1.y, x1.z, x1.w};
#pragma unroll
            for (int mi = 0; mi < 8; mi++) {
                const unsigned long long xp = pack2(xm[mi]);
#pragma unroll
                for (int jj = 0; jj < 8; jj++)
                    acc[mi][jj] = ffma2(xp, w[jj], acc[mi][jj]);
            }
        }
        cp_wait_all();
        __syncthreads();
    }

    // ---- epilogue ----
    // thread's j for pair jj: j = tx*4 + (jj>>1)*64 + (jj&1)*2
#pragma unroll 1
    for (int i = 0; i < 8; i++) {
        const int m = ty * 8 + i;
        const int p = p0 + (m >> 4);
        const int a = a0 + (m & 15);
        const float* bsp = bscore + ((b * L_ + p) * NC_) * L_ + a;
        const float c0 = bsp[0];
        const float c1 = bsp[L_];
        const float c2 = bsp[2 * L_];
        const float c3 = bsp[3 * L_];
        float partial = 0.0f;
#pragma unroll
        for (int jj = 0; jj < 8; jj++) {
            float lo, hi;
            unpack2(acc[i][jj], lo, hi);
            const int j = tx * 4 + (jj >> 1) * 64 + (jj & 1) * 2;
            float t0 = lo + S.bmid[j];
            t0 = fmaf(c0, S.Wtail[0][j], t0);
            t0 = fmaf(c1, S.Wtail[1][j], t0);
            t0 = fmaf(c2, S.Wtail[2][j], t0);
            t0 = fmaf(c3, S.Wtail[3][j], t0);
            float t1 = hi + S.bmid[j + 1];
            t1 = fmaf(c0, S.Wtail[0][j + 1], t1);
            t1 = fmaf(c1, S.Wtail[1][j + 1], t1);
            t1 = fmaf(c2, S.Wtail[2][j + 1], t1);
            t1 = fmaf(c3, S.Wtail[3][j + 1], t1);
            partial = fmaf(fast_tanh(t0), S.Wout[j], partial);
            partial = fmaf(fast_tanh(t1), S.Wout[j + 1], partial);
        }
#pragma unroll
        for (int off = 8; off > 0; off >>= 1)
            partial += __shfl_down_sync(0xFFFFFFFFu, partial, off, 16);
        if (tx == 0)
            out[((b * L_ + p) * NC_ + n) * L_ + a] = partial;
    }
}

// ---------------------------------------------------------------------------
// Launch
// ---------------------------------------------------------------------------
extern "C" void kernel_launch(void* const* d_in, const int* in_sizes, int n_in,
                              void* d_out, int out_size) {
    const float* seq    = (const float*)d_in[0];
    const float* bscore = (const float*)d_in[1];
    const float* Wp     = (const float*)d_in[2];
    const float* bp     = (const float*)d_in[3];
    const float* Wa     = (const float*)d_in[4];
    const float* ba     = (const float*)d_in[5];
    const float* Wmid   = (const float*)d_in[6];
    const float* bmid   = (const float*)d_in[7];
    const float* Wout   = (const float*)d_in[8];
    float* out = (float*)d_out;

    proj_kernel<<<dim3((H_ + NC_ * H_) / 64, (B_ * L_) / 64), 256>>>(
        seq, Wp, bp, Wa, ba);

    cudaFuncSetAttribute(refine_kernel,
                         cudaFuncAttributeMaxDynamicSharedMemorySize,
                         (int)sizeof(SmemT));
    refine_kernel<<<dim3(L_ / 16, L_ / 8, B_ * NC_), 256, sizeof(SmemT)>>>(
        bscore, Wmid, bmid, Wout, out);
}

// round 3
// speedup vs baseline: 1.4685x; 1.0112x over previous
#include <cuda_runtime.h>
#include <cstdint>

// Problem constants (fixed by the dataset)
#define B_  2
#define L_  192
#define D_  768
#define NC_ 4
#define H_  256
#define KC  16      // k-chunk size in refine kernel
#define NT  512     // threads per refine block

// Scratch for projection outputs (no cudaMalloc allowed)
__device__ float g_hp[B_ * L_ * H_];            // [B*L, H]
__device__ float g_ha[B_ * L_ * NC_ * H_];      // [B*L, NC*H]

// ---------------------------------------------------------------------------
// Helpers
// ---------------------------------------------------------------------------
__device__ __forceinline__ float fast_tanh(float x) {
    float e = __expf(2.0f * x);
    return 1.0f - __fdividef(2.0f, e + 1.0f);
}

__device__ __forceinline__ unsigned long long pack2(float x) {
    unsigned long long r;
    asm("mov.b64 %0, {%1, %1};" : "=l"(r) : "f"(x));
    return r;
}

__device__ __forceinline__ unsigned long long ffma2(unsigned long long a,
                                                    unsigned long long b,
                                                    unsigned long long c) {
    unsigned long long d;
    asm("fma.rn.f32x2 %0, %1, %2, %3;" : "=l"(d) : "l"(a), "l"(b), "l"(c));
    return d;
}

__device__ __forceinline__ void unpack2(unsigned long long v, float& lo, float& hi) {
    asm("mov.b64 {%0, %1}, %2;" : "=f"(lo), "=f"(hi) : "l"(v));
}

__device__ __forceinline__ void cp_async16(uint32_t smem, const void* gptr) {
    asm volatile("cp.async.cg.shared.global [%0], [%1], 16;" :: "r"(smem), "l"(gptr));
}
__device__ __forceinline__ void cp_commit() {
    asm volatile("cp.async.commit_group;");
}
__device__ __forceinline__ void cp_wait_all() {
    asm volatile("cp.async.wait_group 0;" ::: "memory");
}

// ---------------------------------------------------------------------------
// Kernel 1: projections  h_p = seq@Wp + bp, h_a = seq@Wa + ba
// ---------------------------------------------------------------------------
__global__ __launch_bounds__(256) void proj_kernel(
    const float* __restrict__ seq,
    const float* __restrict__ Wp, const float* __restrict__ bp,
    const float* __restrict__ Wa, const float* __restrict__ ba)
{
    __shared__ __align__(16) float As[16][68];   // [k][m], padded
    __shared__ __align__(16) float Bs[16][64];   // [k][n]

    const int tid = threadIdx.x;
    const int tx = tid & 15;
    const int ty = tid >> 4;
    const int m0 = blockIdx.y * 64;
    const int n0 = blockIdx.x * 64;

    const float* Wsrc;
    int ld, coff;
    if (n0 < H_) { Wsrc = Wp; ld = H_;        coff = n0; }
    else         { Wsrc = Wa; ld = NC_ * H_;  coff = n0 - H_; }

    float acc[4][4];
#pragma unroll
    for (int i = 0; i < 4; i++)
#pragma unroll
        for (int j = 0; j < 4; j++) acc[i][j] = 0.0f;

#pragma unroll 1
    for (int kc = 0; kc < D_; kc += 16) {
        __syncthreads();
        {
            const int k = tid & 15, mloc = tid >> 4;
#pragma unroll
            for (int ps = 0; ps < 4; ps++) {
                const int m = mloc + ps * 16;
                As[k][m] = seq[(m0 + m) * D_ + kc + k];
            }
        }
        {
            const int c = tid & 63, kr = tid >> 6;
#pragma unroll
            for (int ps = 0; ps < 4; ps++) {
                const int k = kr + ps * 4;
                Bs[k][c] = Wsrc[(kc + k) * ld + coff + c];
            }
        }
        __syncthreads();
#pragma unroll
        for (int k = 0; k < 16; k++) {
            const float4 a4 = *(const float4*)&As[k][ty * 4];
            const float4 b4 = *(const float4*)&Bs[k][tx * 4];
            const float av[4] = {a4.x, a4.y, a4.z, a4.w};
            const float bv[4] = {b4.x, b4.y, b4.z, b4.w};
#pragma unroll
            for (int i = 0; i < 4; i++)
#pragma unroll
                for (int j = 0; j < 4; j++)
                    acc[i][j] = fmaf(av[i], bv[j], acc[i][j]);
        }
    }

#pragma unroll
    for (int i = 0; i < 4; i++) {
        const int r = m0 + ty * 4 + i;
#pragma unroll
        for (int j = 0; j < 4; j++) {
            const int cg = n0 + tx * 4 + j;
            const float v = acc[i][j];
            if (cg < H_) {
                g_hp[r * H_ + cg] = v + bp[cg];
            } else {
                const int c2 = cg - H_;
                g_ha[r * (NC_ * H_) + c2] = v + ba[c2];
            }
        }
    }
}

// ---------------------------------------------------------------------------
// Kernel 2: fused refinement (pipelined, conflict-free SMEM, 512 threads)
// Block: (b, n, 8 p-rows x 16 a-rows) -> M=128, N=256, K=256 in chunks of 16.
// Thread (tx,ty): tx = tid&15 owns N cols {tx*4 + 64q + 0..3 : q=0..3},
//                 ty = tid>>4 in [0,32) owns M rows [ty*4, ty*4+4).
// ---------------------------------------------------------------------------
struct __align__(16) SmemT {
    float hp[8][256];          // persistent h_p rows
    float ha[16][258];         // persistent h_a rows (pad: bank-split halves)
    float Xs[2][KC][132];      // double-buffered X tile [k][m]
    float Ws[2][KC][256];      // double-buffered W chunk [k][j]
    float Wtail[4][256];
    float bmid[256];
    float Wout[256];
};

__global__ __launch_bounds__(NT, 1) void refine_kernel(
    const float* __restrict__ bscore,   // [B, L, NC, L]
    const float* __restrict__ Wmid,     // [NC, H+NC, H]
    const float* __restrict__ bmid,     // [NC, H]
    const float* __restrict__ Wout,     // [NC, H]
    float* __restrict__ out)            // [B, L, NC, L]
{
    extern __shared__ char smem_raw[];
    SmemT& S = *reinterpret_cast<SmemT*>(smem_raw);

    const int tid = threadIdx.x;
    const int tx = tid & 15;
    const int ty = tid >> 4;        // [0, 32)
    const int bz = blockIdx.z;
    const int b = bz >> 2, n = bz & 3;
    const int p0 = blockIdx.y * 8;
    const int a0 = blockIdx.x * 16;

    const float* Wn = Wmid + n * (H_ + NC_) * H_;
    const float* hp_g = g_hp + (b * L_ + p0) * H_;
    const float* ha_g = g_ha + (b * L_ + a0) * (NC_ * H_) + n * H_;

    // ---- init: persistent tiles + epilogue constants ----
    // hp: 8x256 contiguous -> 512 float4
    {
        const float4* src = (const float4*)hp_g;
        ((float4*)&S.hp[0][0])[tid] = src[tid];
    }
    // ha: 16 rows, global row stride NC_*H_; padded smem rows -> scalar stores
#pragma unroll
    for (int q = 0; q < 2; q++) {
        const int lin = q * NT + tid;
        const int r = lin >> 6, c4 = lin & 63;
        const float4 v = ((const float4*)(ha_g + r * (NC_ * H_)))[c4];
        S.ha[r][c4 * 4 + 0] = v.x;
        S.ha[r][c4 * 4 + 1] = v.y;
        S.ha[r][c4 * 4 + 2] = v.z;
        S.ha[r][c4 * 4 + 3] = v.w;
    }
#pragma unroll
    for (int q = 0; q < 2; q++) {
        const int i = q * NT + tid;
        S.Wtail[i >> 8][i & 255] = Wn[(H_ + (i >> 8)) * H_ + (i & 255)];
    }
    if (tid < 256) {
        S.bmid[tid] = bmid[n * H_ + tid];
        S.Wout[tid] = Wout[n * H_ + tid];
    }
    __syncthreads();

    // build-thread mapping: m = tid&127 (one m-row), 4 k's per thread
    const int bm = tid & 127;
    const int bkoff = (tid >> 7) * 4;
    const int bp_row = bm >> 4;
    const int ba_row = bm & 15;

    // ---- prologue: X chunk 0 + async W chunk 0 ----
    {
        const float4* src = (const float4*)Wn;     // 16x256 = 1024 float4
        uint32_t dst = (uint32_t)__cvta_generic_to_shared(&S.Ws[0][0][0]);
#pragma unroll
        for (int q = 0; q < 2; q++) {
            const int idx = q * NT + tid;
            cp_async16(dst + idx * 16, src + idx);
        }
        cp_commit();
#pragma unroll
        for (int kk = 0; kk < 4; kk++) {
            const int k = bkoff + kk;
            S.Xs[0][k][bm] = fast_tanh(S.hp[bp_row][k] + S.ha[ba_row][k]);
        }
    }
    cp_wait_all();
    __syncthreads();

    unsigned long long acc[4][8];   // [m][j-pair] f32x2
#pragma unroll
    for (int i = 0; i < 4; i++)
#pragma unroll
        for (int j = 0; j < 8; j++) acc[i][j] = 0ull;

#pragma unroll 1
    for (int c = 0; c < H_ / KC; c++) {
        const int buf = c & 1;
        if (c < H_ / KC - 1) {
            // async-load next W chunk
            const float4* src = (const float4*)(Wn + (c + 1) * KC * H_);
            uint32_t dst = (uint32_t)__cvta_generic_to_shared(&S.Ws[buf ^ 1][0][0]);
#pragma unroll
            for (int q = 0; q < 2; q++) {
                const int idx = q * NT + tid;
                cp_async16(dst + idx * 16, src + idx);
            }
            cp_commit();
            // build next X chunk
            const int kg = (c + 1) * KC + bkoff;
#pragma unroll
            for (int kk = 0; kk < 4; kk++) {
                S.Xs[buf ^ 1][bkoff + kk][bm] =
                    fast_tanh(S.hp[bp_row][kg + kk] + S.ha[ba_row][kg + kk]);
            }
        }
        // GEMM on current buffers
#pragma unroll
        for (int k = 0; k < KC; k++) {
            const float4 x0 = *(const float4*)&S.Xs[buf][k][ty * 4];
            const ulonglong2 w0 = *(const ulonglong2*)&S.Ws[buf][k][tx * 4];
            const ulonglong2 w1 = *(const ulonglong2*)&S.Ws[buf][k][tx * 4 + 64];
            const ulonglong2 w2 = *(const ulonglong2*)&S.Ws[buf][k][tx * 4 + 128];
            const ulonglong2 w3 = *(const ulonglong2*)&S.Ws[buf][k][tx * 4 + 192];
            const unsigned long long w[8] = {w0.x, w0.y, w1.x, w1.y,
                                             w2.x, w2.y, w3.x, w3.y};
            const float xm[4] = {x0.x, x0.y, x0.z, x0.w};
#pragma unroll
            for (int mi = 0; mi < 4; mi++) {
                const unsigned long long xp = pack2(xm[mi]);
#pragma unroll
                for (int jj = 0; jj < 8; jj++)
                    acc[mi][jj] = ffma2(xp, w[jj], acc[mi][jj]);
            }
        }
        cp_wait_all();
        __syncthreads();
    }

    // ---- epilogue ----
#pragma unroll 1
    for (int i = 0; i < 4; i++) {
        const int m = ty * 4 + i;
        const int p = p0 + (m >> 4);
        const int a = a0 + (m & 15);
        const float* bsp = bscore + ((b * L_ + p) * NC_) * L_ + a;
        const float c0 = bsp[0];
        const float c1 = bsp[L_];
        const float c2 = bsp[2 * L_];
        const float c3 = bsp[3 * L_];
        float partial = 0.0f;
#pragma unroll
        for (int jj = 0; jj < 8; jj++) {
            float lo, hi;
            unpack2(acc[i][jj], lo, hi);
            const int j = tx * 4 + (jj >> 1) * 64 + (jj & 1) * 2;
            float t0 = lo + S.bmid[j];
            t0 = fmaf(c0, S.Wtail[0][j], t0);
            t0 = fmaf(c1, S.Wtail[1][j], t0);
            t0 = fmaf(c2, S.Wtail[2][j], t0);
            t0 = fmaf(c3, S.Wtail[3][j], t0);
            float t1 = hi + S.bmid[j + 1];
            t1 = fmaf(c0, S.Wtail[0][j + 1], t1);
            t1 = fmaf(c1, S.Wtail[1][j + 1], t1);
            t1 = fmaf(c2, S.Wtail[2][j + 1], t1);
            t1 = fmaf(c3, S.Wtail[3][j + 1], t1);
            partial = fmaf(fast_tanh(t0), S.Wout[j], partial);
            partial = fmaf(fast_tanh(t1), S.Wout[j + 1], partial);
        }
#pragma unroll
        for (int off = 8; off > 0; off >>= 1)
            partial += __shfl_down_sync(0xFFFFFFFFu, partial, off, 16);
        if (tx == 0)
            out[((b * L_ + p) * NC_ + n) * L_ + a] = partial;
    }
}

// ---------------------------------------------------------------------------
// Launch
// ---------------------------------------------------------------------------
extern "C" void kernel_launch(void* const* d_in, const int* in_sizes, int n_in,
                              void* d_out, int out_size) {
    const float* seq    = (const float*)d_in[0];
    const float* bscore = (const float*)d_in[1];
    const float* Wp     = (const float*)d_in[2];
    const float* bp     = (const float*)d_in[3];
    const float* Wa     = (const float*)d_in[4];
    const float* ba     = (const float*)d_in[5];
    const float* Wmid   = (const float*)d_in[6];
    const float* bmid   = (const float*)d_in[7];
    const float* Wout   = (const float*)d_in[8];
    float* out = (float*)d_out;

    proj_kernel<<<dim3((H_ + NC_ * H_) / 64, (B_ * L_) / 64), 256>>>(
        seq, Wp, bp, Wa, ba);

    cudaFuncSetAttribute(refine_kernel,
                         cudaFuncAttributeMaxDynamicSharedMemorySize,
                         (int)sizeof(SmemT));
    refine_kernel<<<dim3(L_ / 16, L_ / 8, B_ * NC_), NT, sizeof(SmemT)>>>(
        bscore, Wmid, bmid, Wout, out);
}

// round 5
// speedup vs baseline: 4.3661x; 2.9732x over previous
#include <cuda_runtime.h>
#include <cuda_bf16.h>
#include <cstdint>

// Problem constants (fixed by the dataset)
#define B_  2
#define L_  192
#define D_  768
#define NC_ 4
#define H_  256

#define KCH     64              // k per chunk
#define NCHUNK  5               // 4 full chunks + tail (bs rows + zero pad)
#define NTHR    512
#define ROWB    144             // padded row stride: 64 bf16 = 128B data + 16B pad

#define WIMG_BYTES (256 * ROWB) // one W half-image: 256 n-rows x 144B

// SMEM layout (byte offsets into dynamic smem)
#define OXB(buf)  ((buf) * 36864)            // X buf: XH at +0, XL at +18432
#define OWB(buf)  (73728 + (buf) * 73728)    // W buf: WH at +0, WL at +36864
#define OBMID     221184
#define OWOUT     222208
#define OPART     223232                      // float[128][4]
#define SMEM_BYTES 225280

// Scratch (no cudaMalloc allowed)
__device__ float g_hp[B_ * L_ * H_];                 // [B*L, H]
__device__ float g_ha[B_ * L_ * NC_ * H_];           // [B*L, NC*H]
__device__ __align__(16) char g_w_img[NC_ * NCHUNK * 2 * WIMG_BYTES];

// ---------------------------------------------------------------------------
// Helpers
// ---------------------------------------------------------------------------
__device__ __forceinline__ float fast_tanh(float x) {
    float e = __expf(2.0f * x);
    return 1.0f - __fdividef(2.0f, e + 1.0f);
}

// pack two floats to bf16x2: LOW half = a, HIGH half = b
__device__ __forceinline__ uint32_t bf16pack(float a, float b) {
    uint32_t r;
    asm("cvt.rn.bf16x2.f32 %0, %1, %2;" : "=r"(r) : "f"(b), "f"(a));
    return r;
}
__device__ __forceinline__ float bf_lo(uint32_t u) { return __uint_as_float(u << 16); }
__device__ __forceinline__ float bf_hi(uint32_t u) { return __uint_as_float(u & 0xFFFF0000u); }

__device__ __forceinline__ void cp_async16(uint32_t smem, const void* gptr) {
    asm volatile("cp.async.cg.shared.global [%0], [%1], 16;" :: "r"(smem), "l"(gptr));
}
__device__ __forceinline__ void cp_commit() { asm volatile("cp.async.commit_group;"); }
__device__ __forceinline__ void cp_wait_all() { asm volatile("cp.async.wait_group 0;" ::: "memory"); }

__device__ __forceinline__ void sts128(uint32_t addr, uint32_t r0, uint32_t r1,
                                       uint32_t r2, uint32_t r3) {
    asm volatile("st.shared.v4.b32 [%0], {%1, %2, %3, %4};"
                 :: "r"(addr), "r"(r0), "r"(r1), "r"(r2), "r"(r3) : "memory");
}

__device__ __forceinline__ void ldsm4(uint32_t* r, uint32_t addr) {
    asm volatile("ldmatrix.sync.aligned.m8n8.x4.shared.b16 {%0,%1,%2,%3}, [%4];"
                 : "=r"(r[0]), "=r"(r[1]), "=r"(r[2]), "=r"(r[3]) : "r"(addr));
}

__device__ __forceinline__ void mma16816(float* d, const uint32_t* a, const uint32_t* b) {
    asm volatile("mma.sync.aligned.m16n8k16.row.col.f32.bf16.bf16.f32 "
                 "{%0,%1,%2,%3}, {%4,%5,%6,%7}, {%8,%9}, {%0,%1,%2,%3};"
                 : "+f"(d[0]), "+f"(d[1]), "+f"(d[2]), "+f"(d[3])
                 : "r"(a[0]), "r"(a[1]), "r"(a[2]), "r"(a[3]),
                   "r"(b[0]), "r"(b[1]));
}

// ---------------------------------------------------------------------------
// Kernel 1: projections  h_p = seq@Wp + bp, h_a = seq@Wa + ba  (fp32)
// ---------------------------------------------------------------------------
__global__ __launch_bounds__(256) void proj_kernel(
    const float* __restrict__ seq,
    const float* __restrict__ Wp, const float* __restrict__ bp,
    const float* __restrict__ Wa, const float* __restrict__ ba)
{
    __shared__ __align__(16) float As[16][68];
    __shared__ __align__(16) float Bs[16][64];

    const int tid = threadIdx.x;
    const int tx = tid & 15;
    const int ty = tid >> 4;
    const int m0 = blockIdx.y * 64;
    const int n0 = blockIdx.x * 64;

    const float* Wsrc;
    int ld, coff;
    if (n0 < H_) { Wsrc = Wp; ld = H_;        coff = n0; }
    else         { Wsrc = Wa; ld = NC_ * H_;  coff = n0 - H_; }

    float acc[4][4];
#pragma unroll
    for (int i = 0; i < 4; i++)
#pragma unroll
        for (int j = 0; j < 4; j++) acc[i][j] = 0.0f;

#pragma unroll 1
    for (int kc = 0; kc < D_; kc += 16) {
        __syncthreads();
        {
            const int k = tid & 15, mloc = tid >> 4;
#pragma unroll
            for (int ps = 0; ps < 4; ps++) {
                const int m = mloc + ps * 16;
                As[k][m] = seq[(m0 + m) * D_ + kc + k];
            }
        }
        {
            const int c = tid & 63, kr = tid >> 6;
#pragma unroll
            for (int ps = 0; ps < 4; ps++) {
                const int k = kr + ps * 4;
                Bs[k][c] = Wsrc[(kc + k) * ld + coff + c];
            }
        }
        __syncthreads();
#pragma unroll
        for (int k = 0; k < 16; k++) {
            const float4 a4 = *(const float4*)&As[k][ty * 4];
            const float4 b4 = *(const float4*)&Bs[k][tx * 4];
            const float av[4] = {a4.x, a4.y, a4.z, a4.w};
            const float bv[4] = {b4.x, b4.y, b4.z, b4.w};
#pragma unroll
            for (int i = 0; i < 4; i++)
#pragma unroll
                for (int j = 0; j < 4; j++)
                    acc[i][j] = fmaf(av[i], bv[j], acc[i][j]);
        }
    }

#pragma unroll
    for (int i = 0; i < 4; i++) {
        const int r = m0 + ty * 4 + i;
#pragma unroll
        for (int j = 0; j < 4; j++) {
            const int cg = n0 + tx * 4 + j;
            const float v = acc[i][j];
            if (cg < H_) g_hp[r * H_ + cg] = v + bp[cg];
            else {
                const int c2 = cg - H_;
                g_ha[r * (NC_ * H_) + c2] = v + ba[c2];
            }
        }
    }
}

// ---------------------------------------------------------------------------
// Kernel 1b: split Wmid -> bf16 hi/lo images, [n-row][k] rows padded to 144B.
// grid = NC_*NCHUNK, 256 threads (thread = n row j).
// ---------------------------------------------------------------------------
__global__ void wsplit_kernel(const float* __restrict__ Wmid) {
    const int n = blockIdx.x / NCHUNK, c = blockIdx.x % NCHUNK;
    const int j = threadIdx.x;
    char* imgH = g_w_img + (size_t)((n * NCHUNK + c) * 2) * WIMG_BYTES;
    char* imgL = imgH + WIMG_BYTES;
#pragma unroll 1
    for (int kp = 0; kp < 32; kp++) {
        const int k0 = c * KCH + kp * 2;
        const float w0 = (k0     < H_ + NC_) ? Wmid[(n * (H_ + NC_) + k0    ) * H_ + j] : 0.0f;
        const float w1 = (k0 + 1 < H_ + NC_) ? Wmid[(n * (H_ + NC_) + k0 + 1) * H_ + j] : 0.0f;
        const uint32_t h = bf16pack(w0, w1);
        const uint32_t l = bf16pack(w0 - bf_lo(h), w1 - bf_hi(h));
        *(uint32_t*)(imgH + j * ROWB + kp * 4) = h;
        *(uint32_t*)(imgL + j * ROWB + kp * 4) = l;
    }
    // zero the 16B pad so cp.async source is fully defined
    *(uint4*)(imgH + j * ROWB + 128) = make_uint4(0, 0, 0, 0);
    *(uint4*)(imgL + j * ROWB + 128) = make_uint4(0, 0, 0, 0);
}

// ---------------------------------------------------------------------------
// Kernel 2: refinement via mma.sync m16n8k16 bf16 (split hi/lo, 3 terms).
// Block (b, n, 8p x 16a): D[128,256] = X[128,272] @ W[272,256], K chunks of 64.
// 512 threads = 16 warps, 4(M)x4(N), warp tile 32x64.
// ---------------------------------------------------------------------------
__global__ __launch_bounds__(NTHR, 1) void refine_kernel(
    const float* __restrict__ bscore,   // [B, L, NC, L]
    const float* __restrict__ bmid,     // [NC, H]
    const float* __restrict__ Wout,     // [NC, H]
    float* __restrict__ out)            // [B, L, NC, L]
{
    extern __shared__ __align__(16) char sm[];
    const uint32_t base = (uint32_t)__cvta_generic_to_shared(sm);

    float* bmid_s = (float*)(sm + OBMID);
    float* wout_s = (float*)(sm + OWOUT);
    float* part_s = (float*)(sm + OPART);   // [128][4]

    const int tid = threadIdx.x;
    const int wid = tid >> 5;
    const int lane = tid & 31;
    const int bz = blockIdx.z;
    const int b = bz >> 2, n = bz & 3;
    const int p0 = blockIdx.y * 8;
    const int a0 = blockIdx.x * 16;

    const int mwarp = (wid & 3) * 32;
    const int nwarp = (wid >> 2) * 64;

    // epilogue tables
    if (tid < 256) {
        bmid_s[tid] = bmid[n * H_ + tid];
        wout_s[tid] = Wout[n * H_ + tid];
    }

    // build-thread mapping: row m = tid>>2, k-quarter kq = (tid&3)*16
    const int bm = tid >> 2;
    const int kq = (tid & 3) * 16;
    const int bp_ = p0 + (bm >> 4);
    const int ba_ = a0 + (bm & 15);
    const float* hp_row = g_hp + (b * L_ + bp_) * H_;
    const float* ha_row = g_ha + ((b * L_ + ba_) * NC_ + n) * H_;

    // lane-constant ldmatrix address offsets
    const uint32_t a_off = (uint32_t)((mwarp + (lane & 15)) * ROWB + ((lane >> 4) << 4));
    const uint32_t b_off = (uint32_t)((nwarp + (lane & 7) + ((lane & 16) ? 8 : 0)) * ROWB
                                      + ((lane & 8) ? 16 : 0));

    // ---- X build for chunk c into buffer buf ----
    auto buildX = [&](int c, int buf) {
        const uint32_t xh = base + OXB(buf) + (uint32_t)(bm * ROWB + kq * 2);
        const uint32_t xl = xh + 18432;
        if (c < 4) {
            const float4* hp4 = (const float4*)(hp_row + c * KCH + kq);
            const float4* ha4 = (const float4*)(ha_row + c * KCH + kq);
            uint32_t hw[8], lw[8];
#pragma unroll
            for (int g = 0; g < 4; g++) {
                const float4 u = hp4[g];
                const float4 v = ha4[g];
                const float x0 = fast_tanh(u.x + v.x);
                const float x1 = fast_tanh(u.y + v.y);
                const float x2 = fast_tanh(u.z + v.z);
                const float x3 = fast_tanh(u.w + v.w);
                const uint32_t hA = bf16pack(x0, x1);
                const uint32_t hB = bf16pack(x2, x3);
                hw[g * 2 + 0] = hA;
                hw[g * 2 + 1] = hB;
                lw[g * 2 + 0] = bf16pack(x0 - bf_lo(hA), x1 - bf_hi(hA));
                lw[g * 2 + 1] = bf16pack(x2 - bf_lo(hB), x3 - bf_hi(hB));
            }
            sts128(xh,      hw[0], hw[1], hw[2], hw[3]);
            sts128(xh + 16, hw[4], hw[5], hw[6], hw[7]);
            sts128(xl,      lw[0], lw[1], lw[2], lw[3]);
            sts128(xl + 16, lw[4], lw[5], lw[6], lw[7]);
        } else if (kq == 0) {
            // tail: k 256..259 = bs, 260..271 = 0 (only ks=0 is consumed)
            const float* bsp = bscore + ((b * L_ + bp_) * NC_) * L_ + ba_;
            const float s0 = bsp[0], s1 = bsp[L_], s2 = bsp[2 * L_], s3 = bsp[3 * L_];
            const uint32_t hA = bf16pack(s0, s1);
            const uint32_t hB = bf16pack(s2, s3);
            const uint32_t lA = bf16pack(s0 - bf_lo(hA), s1 - bf_hi(hA));
            const uint32_t lB = bf16pack(s2 - bf_lo(hB), s3 - bf_hi(hB));
            sts128(xh,      hA, hB, 0u, 0u);
            sts128(xh + 16, 0u, 0u, 0u, 0u);
            sts128(xl,      lA, lB, 0u, 0u);
            sts128(xl + 16, 0u, 0u, 0u, 0u);
        }
    };

    // ---- async W copy for chunk c into buffer buf (hi+lo contiguous 72KB) ----
    auto copyW = [&](int c, int buf) {
        const char* src = g_w_img + (size_t)((n * NCHUNK + c) * 2) * WIMG_BYTES;
        const uint32_t dst = base + OWB(buf);
#pragma unroll
        for (int i = 0; i < 9; i++) {
            const int e = i * NTHR + tid;
            cp_async16(dst + e * 16, src + (size_t)e * 16);
        }
        cp_commit();
    };

    float acc[2][8][4];
#pragma unroll
    for (int t = 0; t < 2; t++)
#pragma unroll
        for (int q = 0; q < 8; q++)
#pragma unroll
            for (int r = 0; r < 4; r++) acc[t][q][r] = 0.0f;

    // ---- prologue ----
    copyW(0, 0);
    buildX(0, 0);
    cp_wait_all();
    __syncthreads();

#pragma unroll 1
    for (int c = 0; c < NCHUNK; c++) {
        const int cur = c & 1;
        if (c < NCHUNK - 1) {
            copyW(c + 1, cur ^ 1);
            buildX(c + 1, cur ^ 1);
        }
        const uint32_t xb = base + OXB(cur);
        const uint32_t wb = base + OWB(cur);
        const int nsteps = (c == 4) ? 1 : 4;
        // 3 split segments: (XH,WH), (XL,WH), (XH,WL)
#pragma unroll 1
        for (int seg = 0; seg < 3; seg++) {
            const uint32_t xa = xb + ((seg == 1) ? 18432u : 0u);
            const uint32_t wa = wb + ((seg == 2) ? 36864u : 0u);
#pragma unroll 1
            for (int ks = 0; ks < nsteps; ks++) {
                uint32_t A0[4], A1[4], Bf[4][4];
                const uint32_t kb = (uint32_t)(ks * 32);
                ldsm4(A0, xa + a_off + kb);
                ldsm4(A1, xa + a_off + 16 * ROWB + kb);
#pragma unroll
                for (int q = 0; q < 4; q++)
                    ldsm4(Bf[q], wa + b_off + q * 16 * ROWB + kb);
#pragma unroll
                for (int q2 = 0; q2 < 8; q2++) {
                    const uint32_t* bq = &Bf[q2 >> 1][(q2 & 1) * 2];
                    mma16816(acc[0][q2], A0, bq);
                    mma16816(acc[1][q2], A1, bq);
                }
            }
        }
        if (c < NCHUNK - 1) {
            cp_wait_all();
            __syncthreads();
        }
    }

    // ---- epilogue: tanh(acc + bmid) . Wout, reduce over N ----
    const int g = lane >> 2;
#pragma unroll
    for (int t = 0; t < 2; t++) {
        float p_lo = 0.0f, p_hi = 0.0f;
#pragma unroll
        for (int q2 = 0; q2 < 8; q2++) {
            const int j0 = nwarp + q2 * 8 + (lane & 3) * 2;
            const float bm0 = bmid_s[j0], bm1 = bmid_s[j0 + 1];
            const float wo0 = wout_s[j0], wo1 = wout_s[j0 + 1];
            p_lo = fmaf(fast_tanh(acc[t][q2][0] + bm0), wo0, p_lo);
            p_lo = fmaf(fast_tanh(acc[t][q2][1] + bm1), wo1, p_lo);
            p_hi = fmaf(fast_tanh(acc[t][q2][2] + bm0), wo0, p_hi);
            p_hi = fmaf(fast_tanh(acc[t][q2][3] + bm1), wo1, p_hi);
        }
        p_lo += __shfl_xor_sync(0xFFFFFFFFu, p_lo, 1, 4);
        p_lo += __shfl_xor_sync(0xFFFFFFFFu, p_lo, 2, 4);
        p_hi += __shfl_xor_sync(0xFFFFFFFFu, p_hi, 1, 4);
        p_hi += __shfl_xor_sync(0xFFFFFFFFu, p_hi, 2, 4);
        if ((lane & 3) == 0) {
            const int r0 = mwarp + t * 16 + g;
            part_s[r0 * 4 + (wid >> 2)] = p_lo;
            part_s[(r0 + 8) * 4 + (wid >> 2)] = p_hi;
        }
    }
    __syncthreads();

    if (tid < 128) {
        const float s = part_s[tid * 4] + part_s[tid * 4 + 1]
                      + part_s[tid * 4 + 2] + part_s[tid * 4 + 3];
        const int p = p0 + (tid >> 4);
        const int a = a0 + (tid & 15);
        out[((b * L_ + p) * NC_ + n) * L_ + a] = s;
    }
}

// ---------------------------------------------------------------------------
// Launch
// ---------------------------------------------------------------------------
extern "C" void kernel_launch(void* const* d_in, const int* in_sizes, int n_in,
                              void* d_out, int out_size) {
    const float* seq    = (const float*)d_in[0];
    const float* bscore = (const float*)d_in[1];
    const float* Wp     = (const float*)d_in[2];
    const float* bp     = (const float*)d_in[3];
    const float* Wa     = (const float*)d_in[4];
    const float* ba     = (const float*)d_in[5];
    const float* Wmid   = (const float*)d_in[6];
    const float* bmid   = (const float*)d_in[7];
    const float* Wout   = (const float*)d_in[8];
    float* out = (float*)d_out;

    proj_kernel<<<dim3((H_ + NC_ * H_) / 64, (B_ * L_) / 64), 256>>>(
        seq, Wp, bp, Wa, ba);
    wsplit_kernel<<<NC_ * NCHUNK, 256>>>(Wmid);

    cudaFuncSetAttribute(refine_kernel,
                         cudaFuncAttributeMaxDynamicSharedMemorySize, SMEM_BYTES);
    refine_kernel<<<dim3(L_ / 16, L_ / 8, B_ * NC_), NTHR, SMEM_BYTES>>>(
        bscore, bmid, Wout, out);
}

// round 6
// speedup vs baseline: 4.8399x; 1.1085x over previous
#include <cuda_runtime.h>
#include <cuda_bf16.h>
#include <cstdint>

// Problem constants (fixed by the dataset)
#define B_  2
#define L_  192
#define D_  768
#define NC_ 4
#define H_  256

#define KCH     64              // k per chunk
#define NCHUNK  4               // K = 256 = 4 x 64 (bs tail folded into epilogue)
#define NTHR    512
#define ROWB    144             // padded row stride: 64 bf16 = 128B + 16B pad

#define WIMG_BYTES (256 * ROWB) // one W half-image: 256 n-rows x 144B

// SMEM layout (byte offsets into dynamic smem)
#define OXB(buf)  ((buf) * 36864)            // X buf: XH at +0, XL at +18432
#define OWB(buf)  (73728 + (buf) * 73728)    // W buf: WH at +0, WL at +36864
#define OBMID     221184
#define OWOUT     222208
#define OWTAIL    223232                      // float[4][256]
#define OPART     227328                      // float[128][4]
#define SMEM_BYTES 229376

// Scratch (no cudaMalloc allowed)
__device__ float g_hp[B_ * L_ * H_];                 // [B*L, H]
__device__ float g_ha[B_ * L_ * NC_ * H_];           // [B*L, NC*H]
__device__ __align__(16) char g_w_img[NC_ * NCHUNK * 2 * WIMG_BYTES];

// ---------------------------------------------------------------------------
// Helpers
// ---------------------------------------------------------------------------
__device__ __forceinline__ float fast_tanh(float x) {
    float e = __expf(2.0f * x);
    return 1.0f - __fdividef(2.0f, e + 1.0f);
}

__device__ __forceinline__ uint32_t bf16pack(float a, float b) {
    uint32_t r;
    asm("cvt.rn.bf16x2.f32 %0, %1, %2;" : "=r"(r) : "f"(b), "f"(a));
    return r;
}
__device__ __forceinline__ float bf_lo(uint32_t u) { return __uint_as_float(u << 16); }
__device__ __forceinline__ float bf_hi(uint32_t u) { return __uint_as_float(u & 0xFFFF0000u); }

__device__ __forceinline__ unsigned long long pack2(float x) {
    unsigned long long r;
    asm("mov.b64 %0, {%1, %1};" : "=l"(r) : "f"(x));
    return r;
}
__device__ __forceinline__ unsigned long long ffma2(unsigned long long a,
                                                    unsigned long long b,
                                                    unsigned long long c) {
    unsigned long long d;
    asm("fma.rn.f32x2 %0, %1, %2, %3;" : "=l"(d) : "l"(a), "l"(b), "l"(c));
    return d;
}
__device__ __forceinline__ void unpack2(unsigned long long v, float& lo, float& hi) {
    asm("mov.b64 {%0, %1}, %2;" : "=f"(lo), "=f"(hi) : "l"(v));
}

__device__ __forceinline__ void cp_async16(uint32_t smem, const void* gptr) {
    asm volatile("cp.async.cg.shared.global [%0], [%1], 16;" :: "r"(smem), "l"(gptr));
}
__device__ __forceinline__ void cp_commit() { asm volatile("cp.async.commit_group;"); }
__device__ __forceinline__ void cp_wait_all() { asm volatile("cp.async.wait_group 0;" ::: "memory"); }

__device__ __forceinline__ void sts128(uint32_t addr, uint32_t r0, uint32_t r1,
                                       uint32_t r2, uint32_t r3) {
    asm volatile("st.shared.v4.b32 [%0], {%1, %2, %3, %4};"
                 :: "r"(addr), "r"(r0), "r"(r1), "r"(r2), "r"(r3) : "memory");
}

__device__ __forceinline__ void ldsm4(uint32_t* r, uint32_t addr) {
    asm volatile("ldmatrix.sync.aligned.m8n8.x4.shared.b16 {%0,%1,%2,%3}, [%4];"
                 : "=r"(r[0]), "=r"(r[1]), "=r"(r[2]), "=r"(r[3]) : "r"(addr));
}

__device__ __forceinline__ void mma16816(float* d, const uint32_t* a, const uint32_t* b) {
    asm volatile("mma.sync.aligned.m16n8k16.row.col.f32.bf16.bf16.f32 "
                 "{%0,%1,%2,%3}, {%4,%5,%6,%7}, {%8,%9}, {%0,%1,%2,%3};"
                 : "+f"(d[0]), "+f"(d[1]), "+f"(d[2]), "+f"(d[3])
                 : "r"(a[0]), "r"(a[1]), "r"(a[2]), "r"(a[3]),
                   "r"(b[0]), "r"(b[1]));
}

// ---------------------------------------------------------------------------
// Kernel 1: projections  h_p = seq@Wp + bp, h_a = seq@Wa + ba  (fp32, f32x2)
// Tile 32(m) x 64(n), 256 threads, micro 2x4, grid 20x12 = 240 blocks.
// ---------------------------------------------------------------------------
__global__ __launch_bounds__(256) void proj_kernel(
    const float* __restrict__ seq,
    const float* __restrict__ Wp, const float* __restrict__ bp,
    const float* __restrict__ Wa, const float* __restrict__ ba)
{
    __shared__ __align__(16) float As[16][36];   // [k][m], padded
    __shared__ __align__(16) float Bs[16][64];   // [k][n]

    const int tid = threadIdx.x;
    const int tx = tid & 15;        // 4 n cols: tx*4
    const int ty = tid >> 4;        // 2 m rows: ty*2
    const int m0 = blockIdx.y * 32;
    const int n0 = blockIdx.x * 64;

    const float* Wsrc;
    int ld, coff;
    if (n0 < H_) { Wsrc = Wp; ld = H_;        coff = n0; }
    else         { Wsrc = Wa; ld = NC_ * H_;  coff = n0 - H_; }

    unsigned long long acc2[2][2];
#pragma unroll
    for (int i = 0; i < 2; i++)
#pragma unroll
        for (int j = 0; j < 2; j++) acc2[i][j] = 0ull;

#pragma unroll 1
    for (int kc = 0; kc < D_; kc += 16) {
        __syncthreads();
        {   // A tile: 32 m x 16 k transposed -> As[k][m]; 2 loads/thread
            const int k = tid & 15, mloc = tid >> 4;
            As[k][mloc] = seq[(m0 + mloc) * D_ + kc + k];
            As[k][mloc + 16] = seq[(m0 + mloc + 16) * D_ + kc + k];
        }
        {   // B tile: 16 k x 64 n; 4 loads/thread, coalesced over n
            const int c = tid & 63, kr = tid >> 6;
#pragma unroll
            for (int ps = 0; ps < 4; ps++) {
                const int k = kr + ps * 4;
                Bs[k][c] = Wsrc[(kc + k) * ld + coff + c];
            }
        }
        __syncthreads();
#pragma unroll
        for (int k = 0; k < 16; k++) {
            const float2 a2 = *(const float2*)&As[k][ty * 2];
            const ulonglong2 b2 = *(const ulonglong2*)&Bs[k][tx * 4];
            const unsigned long long p0v = pack2(a2.x);
            const unsigned long long p1v = pack2(a2.y);
            acc2[0][0] = ffma2(p0v, b2.x, acc2[0][0]);
            acc2[0][1] = ffma2(p0v, b2.y, acc2[0][1]);
            acc2[1][0] = ffma2(p1v, b2.x, acc2[1][0]);
            acc2[1][1] = ffma2(p1v, b2.y, acc2[1][1]);
        }
    }

#pragma unroll
    for (int i = 0; i < 2; i++) {
        const int r = m0 + ty * 2 + i;
#pragma unroll
        for (int j = 0; j < 2; j++) {
            float lo, hi;
            unpack2(acc2[i][j], lo, hi);
            const int cg = n0 + tx * 4 + j * 2;
            if (cg < H_) {
                g_hp[r * H_ + cg] = lo + bp[cg];
                g_hp[r * H_ + cg + 1] = hi + bp[cg + 1];
            } else {
                const int c2 = cg - H_;
                g_ha[r * (NC_ * H_) + c2] = lo + ba[c2];
                g_ha[r * (NC_ * H_) + c2 + 1] = hi + ba[c2 + 1];
            }
        }
    }
}

// ---------------------------------------------------------------------------
// Kernel 1b: split Wmid -> bf16 hi/lo images, [n-row][k] rows padded to 144B.
// grid = NC_*NCHUNK, 256 threads (thread = n row j).
// ---------------------------------------------------------------------------
__global__ void wsplit_kernel(const float* __restrict__ Wmid) {
    const int n = blockIdx.x / NCHUNK, c = blockIdx.x % NCHUNK;
    const int j = threadIdx.x;
    char* imgH = g_w_img + (size_t)((n * NCHUNK + c) * 2) * WIMG_BYTES;
    char* imgL = imgH + WIMG_BYTES;
#pragma unroll 1
    for (int kp = 0; kp < 32; kp++) {
        const int k0 = c * KCH + kp * 2;
        const float w0 = Wmid[(n * (H_ + NC_) + k0    ) * H_ + j];
        const float w1 = Wmid[(n * (H_ + NC_) + k0 + 1) * H_ + j];
        const uint32_t h = bf16pack(w0, w1);
        const uint32_t l = bf16pack(w0 - bf_lo(h), w1 - bf_hi(h));
        *(uint32_t*)(imgH + j * ROWB + kp * 4) = h;
        *(uint32_t*)(imgL + j * ROWB + kp * 4) = l;
    }
    *(uint4*)(imgH + j * ROWB + 128) = make_uint4(0, 0, 0, 0);
    *(uint4*)(imgL + j * ROWB + 128) = make_uint4(0, 0, 0, 0);
}

// ---------------------------------------------------------------------------
// Kernel 2: refinement via mma.sync m16n8k16 bf16 (split hi/lo, 3 terms).
// Block (b, n, 8p x 16a): D[128,256] = X[128,256] @ W[256,256] + bs-tail (epi).
// 512 threads = 16 warps, 4(M)x4(N), warp tile 32x64.
// ---------------------------------------------------------------------------
__global__ __launch_bounds__(NTHR, 1) void refine_kernel(
    const float* __restrict__ bscore,   // [B, L, NC, L]
    const float* __restrict__ Wmid,     // [NC, H+NC, H]
    const float* __restrict__ bmid,     // [NC, H]
    const float* __restrict__ Wout,     // [NC, H]
    float* __restrict__ out)            // [B, L, NC, L]
{
    extern __shared__ __align__(16) char sm[];
    const uint32_t base = (uint32_t)__cvta_generic_to_shared(sm);

    float* bmid_s  = (float*)(sm + OBMID);
    float* wout_s  = (float*)(sm + OWOUT);
    float* wtail_s = (float*)(sm + OWTAIL);  // [4][256]
    float* part_s  = (float*)(sm + OPART);   // [128][4]

    const int tid = threadIdx.x;
    const int wid = tid >> 5;
    const int lane = tid & 31;
    const int bz = blockIdx.z;
    const int b = bz >> 2, n = bz & 3;
    const int p0 = blockIdx.y * 8;
    const int a0 = blockIdx.x * 16;

    const int mwarp = (wid & 3) * 32;
    const int nwarp = (wid >> 2) * 64;

    // epilogue tables
    if (tid < 256) {
        bmid_s[tid] = bmid[n * H_ + tid];
        wout_s[tid] = Wout[n * H_ + tid];
    }
#pragma unroll
    for (int q = 0; q < 2; q++) {
        const int i = q * NTHR + tid;
        wtail_s[i] = Wmid[(n * (H_ + NC_) + H_ + (i >> 8)) * H_ + (i & 255)];
    }

    // build-thread mapping: row m = tid>>2, k-quarter kq = (tid&3)*16
    const int bm = tid >> 2;
    const int kq = (tid & 3) * 16;
    const int bp_ = p0 + (bm >> 4);
    const int ba_ = a0 + (bm & 15);
    const float* hp_row = g_hp + (b * L_ + bp_) * H_;
    const float* ha_row = g_ha + ((b * L_ + ba_) * NC_ + n) * H_;

    // lane-constant ldmatrix address offsets
    const uint32_t a_off = (uint32_t)((mwarp + (lane & 15)) * ROWB + ((lane >> 4) << 4));
    const uint32_t b_off = (uint32_t)((nwarp + (lane & 7) + ((lane & 16) ? 8 : 0)) * ROWB
                                      + ((lane & 8) ? 16 : 0));

    auto buildX = [&](int c, int buf) {
        const uint32_t xh = base + OXB(buf) + (uint32_t)(bm * ROWB + kq * 2);
        const uint32_t xl = xh + 18432;
        const float4* hp4 = (const float4*)(hp_row + c * KCH + kq);
        const float4* ha4 = (const float4*)(ha_row + c * KCH + kq);
        uint32_t hw[8], lw[8];
#pragma unroll
        for (int g = 0; g < 4; g++) {
            const float4 u = hp4[g];
            const float4 v = ha4[g];
            const float x0 = fast_tanh(u.x + v.x);
            const float x1 = fast_tanh(u.y + v.y);
            const float x2 = fast_tanh(u.z + v.z);
            const float x3 = fast_tanh(u.w + v.w);
            const uint32_t hA = bf16pack(x0, x1);
            const uint32_t hB = bf16pack(x2, x3);
            hw[g * 2 + 0] = hA;
            hw[g * 2 + 1] = hB;
            lw[g * 2 + 0] = bf16pack(x0 - bf_lo(hA), x1 - bf_hi(hA));
            lw[g * 2 + 1] = bf16pack(x2 - bf_lo(hB), x3 - bf_hi(hB));
        }
        sts128(xh,      hw[0], hw[1], hw[2], hw[3]);
        sts128(xh + 16, hw[4], hw[5], hw[6], hw[7]);
        sts128(xl,      lw[0], lw[1], lw[2], lw[3]);
        sts128(xl + 16, lw[4], lw[5], lw[6], lw[7]);
    };

    auto copyW = [&](int c, int buf) {
        const char* src = g_w_img + (size_t)((n * NCHUNK + c) * 2) * WIMG_BYTES;
        const uint32_t dst = base + OWB(buf);
#pragma unroll
        for (int i = 0; i < 9; i++) {
            const int e = i * NTHR + tid;
            cp_async16(dst + e * 16, src + (size_t)e * 16);
        }
        cp_commit();
    };

    float acc[2][8][4];
#pragma unroll
    for (int t = 0; t < 2; t++)
#pragma unroll
        for (int q = 0; q < 8; q++)
#pragma unroll
            for (int r = 0; r < 4; r++) acc[t][q][r] = 0.0f;

    // one k16-step: shared fragments across the 3 split segments
    auto mma_ks = [&](int ks, uint32_t xb, uint32_t wb) {
        uint32_t AH0[4], AH1[4], AL0[4], AL1[4], Bf[4][4];
        const uint32_t kb = (uint32_t)(ks * 32);
        ldsm4(AH0, xb + a_off + kb);
        ldsm4(AH1, xb + a_off + 16 * ROWB + kb);
        ldsm4(AL0, xb + 18432 + a_off + kb);
        ldsm4(AL1, xb + 18432 + a_off + 16 * ROWB + kb);
#pragma unroll
        for (int q = 0; q < 4; q++)
            ldsm4(Bf[q], wb + b_off + q * 16 * ROWB + kb);
        // seg0 (XH*WH) + seg1 (XL*WH)
#pragma unroll
        for (int q2 = 0; q2 < 8; q2++) {
            const uint32_t* bq = &Bf[q2 >> 1][(q2 & 1) * 2];
            mma16816(acc[0][q2], AH0, bq);
            mma16816(acc[1][q2], AH1, bq);
            mma16816(acc[0][q2], AL0, bq);
            mma16816(acc[1][q2], AL1, bq);
        }
        // seg2 (XH*WL): reload B frags from WL
#pragma unroll
        for (int q = 0; q < 4; q++)
            ldsm4(Bf[q], wb + 36864 + b_off + q * 16 * ROWB + kb);
#pragma unroll
        for (int q2 = 0; q2 < 8; q2++) {
            const uint32_t* bq = &Bf[q2 >> 1][(q2 & 1) * 2];
            mma16816(acc[0][q2], AH0, bq);
            mma16816(acc[1][q2], AH1, bq);
        }
    };

    // ---- prologue ----
    copyW(0, 0);
    buildX(0, 0);
    cp_wait_all();
    __syncthreads();

#pragma unroll 1
    for (int c = 0; c < NCHUNK; c++) {
        const int cur = c & 1;
        const uint32_t xb = base + OXB(cur);
        const uint32_t wb = base + OWB(cur);
        if (c < NCHUNK - 1) copyW(c + 1, cur ^ 1);
        mma_ks(0, xb, wb);
        mma_ks(1, xb, wb);
        if (c < NCHUNK - 1) buildX(c + 1, cur ^ 1);
        mma_ks(2, xb, wb);
        mma_ks(3, xb, wb);
        if (c < NCHUNK - 1) {
            cp_wait_all();
            __syncthreads();
        }
    }

    // ---- epilogue: +bs-tail +bmid, tanh, dot Wout, reduce over N ----
    const int g = lane >> 2;
    // bs values for this thread's 4 rows: [t][h][ct]
    float bsv[2][2][4];
#pragma unroll
    for (int t = 0; t < 2; t++)
#pragma unroll
        for (int h = 0; h < 2; h++) {
            const int row = mwarp + t * 16 + g + h * 8;
            const float* bsp = bscore
                + ((b * L_ + p0 + (row >> 4)) * NC_) * L_ + a0 + (row & 15);
#pragma unroll
            for (int ct = 0; ct < 4; ct++) bsv[t][h][ct] = bsp[ct * L_];
        }

    float part[2][2] = {{0.0f, 0.0f}, {0.0f, 0.0f}};
#pragma unroll
    for (int q2 = 0; q2 < 8; q2++) {
        const int j0 = nwarp + q2 * 8 + (lane & 3) * 2;
        const float bm0 = bmid_s[j0], bm1 = bmid_s[j0 + 1];
        const float wo0 = wout_s[j0], wo1 = wout_s[j0 + 1];
        float wt0[4], wt1[4];
#pragma unroll
        for (int ct = 0; ct < 4; ct++) {
            wt0[ct] = wtail_s[ct * 256 + j0];
            wt1[ct] = wtail_s[ct * 256 + j0 + 1];
        }
#pragma unroll
        for (int t = 0; t < 2; t++)
#pragma unroll
            for (int h = 0; h < 2; h++) {
                float v0 = acc[t][q2][h * 2 + 0] + bm0;
                float v1 = acc[t][q2][h * 2 + 1] + bm1;
#pragma unroll
                for (int ct = 0; ct < 4; ct++) {
                    v0 = fmaf(bsv[t][h][ct], wt0[ct], v0);
                    v1 = fmaf(bsv[t][h][ct], wt1[ct], v1);
                }
                part[t][h] = fmaf(fast_tanh(v0), wo0, part[t][h]);
                part[t][h] = fmaf(fast_tanh(v1), wo1, part[t][h]);
            }
    }
#pragma unroll
    for (int t = 0; t < 2; t++)
#pragma unroll
        for (int h = 0; h < 2; h++) {
            float v = part[t][h];
            v += __shfl_xor_sync(0xFFFFFFFFu, v, 1, 4);
            v += __shfl_xor_sync(0xFFFFFFFFu, v, 2, 4);
            if ((lane & 3) == 0) {
                const int r0 = mwarp + t * 16 + g + h * 8;
                part_s[r0 * 4 + (wid >> 2)] = v;
            }
        }
    __syncthreads();

    if (tid < 128) {
        const float s = part_s[tid * 4] + part_s[tid * 4 + 1]
                      + part_s[tid * 4 + 2] + part_s[tid * 4 + 3];
        const int p = p0 + (tid >> 4);
        const int a = a0 + (tid & 15);
        out[((b * L_ + p) * NC_ + n) * L_ + a] = s;
    }
}

// ---------------------------------------------------------------------------
// Launch
// ---------------------------------------------------------------------------
extern "C" void kernel_launch(void* const* d_in, const int* in_sizes, int n_in,
                              void* d_out, int out_size) {
    const float* seq    = (const float*)d_in[0];
    const float* bscore = (const float*)d_in[1];
    const float* Wp     = (const float*)d_in[2];
    const float* bp     = (const float*)d_in[3];
    const float* Wa     = (const float*)d_in[4];
    const float* ba     = (const float*)d_in[5];
    const float* Wmid   = (const float*)d_in[6];
    const float* bmid   = (const float*)d_in[7];
    const float* Wout   = (const float*)d_in[8];
    float* out = (float*)d_out;

    proj_kernel<<<dim3((H_ + NC_ * H_) / 64, (B_ * L_) / 32), 256>>>(
        seq, Wp, bp, Wa, ba);
    wsplit_kernel<<<NC_ * NCHUNK, 256>>>(Wmid);

    cudaFuncSetAttribute(refine_kernel,
                         cudaFuncAttributeMaxDynamicSharedMemorySize, SMEM_BYTES);
    refine_kernel<<<dim3(L_ / 16, L_ / 8, B_ * NC_), NTHR, SMEM_BYTES>>>(
        bscore, Wmid, bmid, Wout, out);
}